// round 2
// baseline (speedup 1.0000x reference)
#include <cuda_runtime.h>
#include <cuda_bf16.h>
#include <math.h>
#include <stdint.h>

// ---------------------------------------------------------------------------
// Problem constants
// ---------------------------------------------------------------------------
#define BATCH   2
#define CH      192
#define DIM     32
#define SPAT    (DIM*DIM*DIM)      // 32768
#define HID     768
#define KS      7
#define KV      343
#define NCELLS  1024               // 2 * 8*8*8
#define CELLTOK 64                 // 4*4*4

// ---------------------------------------------------------------------------
// Device scratch (static globals -- no runtime allocation)
// ---------------------------------------------------------------------------
__device__ int   g_cellList[NCELLS];
__device__ int   g_cellCount;
__device__ float g_yc[(size_t)NCELLS * CELLTOK * CH];    // compacted conv out
__device__ float g_h [(size_t)NCELLS * CELLTOK * HID];   // hidden activations

// ---------------------------------------------------------------------------
// Helpers
// ---------------------------------------------------------------------------
__device__ __forceinline__ float2 ffma2(float2 a, float2 b, float2 c) {
    union U { float2 f; unsigned long long u; };
    U A, B, C, D;
    A.f = a; B.f = b; C.f = c;
    asm("fma.rn.f32x2 %0, %1, %2, %3;" : "=l"(D.u) : "l"(A.u), "l"(B.u), "l"(C.u));
    return D.f;
}

__device__ __forceinline__ float tf32r(float x) {
    unsigned int u;
    asm("cvt.rna.tf32.f32 %0, %1;" : "=r"(u) : "f"(x));
    return __uint_as_float(u);
}

// mma.sync m16n8k8 tf32: d += a * b
// a0:(g,t) a1:(g+8,t) a2:(g,t+4) a3:(g+8,t+4); b0:(t,g) b1:(t+4,g)
// c0:(g,2t) c1:(g,2t+1) c2:(g+8,2t) c3:(g+8,2t+1)   [g=lane>>2, t=lane&3]
__device__ __forceinline__ void mma_tf32(float* d, const float* a, float b0, float b1) {
    asm volatile(
        "mma.sync.aligned.m16n8k8.row.col.f32.tf32.tf32.f32 "
        "{%0,%1,%2,%3}, {%4,%5,%6,%7}, {%8,%9}, {%0,%1,%2,%3};"
        : "+f"(d[0]), "+f"(d[1]), "+f"(d[2]), "+f"(d[3])
        : "r"(__float_as_uint(a[0])), "r"(__float_as_uint(a[1])),
          "r"(__float_as_uint(a[2])), "r"(__float_as_uint(a[3])),
          "r"(__float_as_uint(b0)),   "r"(__float_as_uint(b1)));
}

__device__ __forceinline__ float gelu_exact(float x) {
    return 0.5f * x * (1.0f + erff(x * 0.70710678118654752f));
}

// ---------------------------------------------------------------------------
// Kernel 0: build compacted active-cell list. Robust to mask dtype
// (int32 / uint8 / float32) via runtime content sniffing.
// ---------------------------------------------------------------------------
__global__ void build_cells_kernel(const void* __restrict__ maskp) {
    __shared__ int s_float, s_byte;
    __shared__ int wsum[32];
    int tid = threadIdx.x;                 // 0..1023 = flat cell id
    if (tid == 0) { s_float = 0; s_byte = 0; }
    __syncthreads();
    if (tid < 256) {
        unsigned w = ((const unsigned*)maskp)[tid];
        if (w == 0x3F800000u) atomicOr(&s_float, 1);
        else if (w > 1u)      atomicOr(&s_byte, 1);
    }
    __syncthreads();
    int active;
    if (s_float)      active = (((const float*)maskp)[tid] != 0.0f) ? 1 : 0;
    else if (s_byte)  active = (((const unsigned char*)maskp)[tid] != 0) ? 1 : 0;
    else              active = (((const int*)maskp)[tid] != 0) ? 1 : 0;

    unsigned bal = __ballot_sync(0xffffffffu, active);
    int lane = tid & 31, wid = tid >> 5;
    int pre = __popc(bal & ((1u << lane) - 1u));
    if (lane == 31) wsum[wid] = pre + active;
    __syncthreads();
    if (wid == 0) {
        int v = wsum[lane];
        #pragma unroll
        for (int off = 1; off < 32; off <<= 1) {
            int t = __shfl_up_sync(0xffffffffu, v, off);
            if (lane >= off) v += t;
        }
        wsum[lane] = v;       // inclusive
    }
    __syncthreads();
    int base = (wid == 0) ? 0 : wsum[wid - 1];
    if (active) g_cellList[base + pre] = tid;
    if (tid == 1023) g_cellCount = wsum[31];
}

// ---------------------------------------------------------------------------
// Kernel 1: depthwise 7^3 conv on active cells, channel pairs via FFMA2.
// Block = (1 cell) x (16 channels). 128 threads.
// ---------------------------------------------------------------------------
#define CONV_TILE_F2 1200                         // 10*10*12 float2 per pair
#define CONV_TILE_B  (8 * CONV_TILE_F2 * 8)       // 76800
#define CONV_WGT_B   (8 * 344 * 8)                // 22016
#define CONV_SOUT_B  (64 * 16 * 4)                // 4096
#define CONV_SMEM    (CONV_TILE_B + CONV_WGT_B + CONV_SOUT_B)

__global__ __launch_bounds__(128)
void conv_kernel(const float* __restrict__ x,
                 const float* __restrict__ dw_w,
                 const float* __restrict__ dw_b) {
    int cellSlot = blockIdx.x / 12;
    if (cellSlot >= g_cellCount) return;
    int pg   = blockIdx.x % 12;
    int cell = g_cellList[cellSlot];
    int b  = cell >> 9;
    int cz = (cell >> 6) & 7, cy = (cell >> 3) & 7, cx = cell & 7;
    int z0 = cz * 4, y0 = cy * 4, x0 = cx * 4;
    int c0 = pg * 16;

    extern __shared__ char sm[];
    float2* tile = (float2*)sm;
    float2* wgt  = (float2*)(sm + CONV_TILE_B);
    float*  sOut = (float*)(sm + CONV_TILE_B + CONV_WGT_B);

    int tid = threadIdx.x;
    const float* xb = x + (size_t)b * CH * SPAT;

    // stage input tiles (zero-padded halo): 8 pairs x 10x10x(10 of 12)
    for (int idx = tid; idx < 8 * 1000; idx += 128) {
        int p  = idx / 1000;
        int s  = idx - p * 1000;
        int zi = s / 100;
        int r  = s - zi * 100;
        int yi = r / 10;
        int xi = r - yi * 10;
        int gz = z0 + zi - 3, gy = y0 + yi - 3, gx = x0 + xi - 3;
        float v0 = 0.f, v1 = 0.f;
        if (gz >= 0 && gz < DIM && gy >= 0 && gy < DIM && gx >= 0 && gx < DIM) {
            size_t off = (size_t)(c0 + 2 * p) * SPAT + gz * 1024 + gy * 32 + gx;
            v0 = xb[off];
            v1 = xb[off + SPAT];
        }
        tile[p * CONV_TILE_F2 + (zi * 10 + yi) * 12 + xi] = make_float2(v0, v1);
    }
    for (int idx = tid; idx < 8 * KV; idx += 128) {
        int p = idx / KV;
        int t = idx - p * KV;
        wgt[p * 344 + t] = make_float2(dw_w[(c0 + 2 * p) * KV + t],
                                       dw_w[(c0 + 2 * p + 1) * KV + t]);
    }
    __syncthreads();

    int p  = tid >> 4;        // channel pair 0..7
    int z  = (tid >> 2) & 3;  // out z 0..3
    int yy = tid & 3;         // out y 0..3
    float2 bias = make_float2(dw_b[c0 + 2 * p], dw_b[c0 + 2 * p + 1]);
    float2 acc0 = bias, acc1 = bias, acc2 = bias, acc3 = bias;

    const float2* tp = tile + p * CONV_TILE_F2;
    const float2* wp = wgt + p * 344;

    for (int dz = 0; dz < 7; dz++) {
        for (int dy = 0; dy < 7; dy++) {
            const float2* row = tp + ((z + dz) * 10 + (yy + dy)) * 12;
            float4 q0 = *(const float4*)(row + 0);
            float4 q1 = *(const float4*)(row + 2);
            float4 q2 = *(const float4*)(row + 4);
            float4 q3 = *(const float4*)(row + 6);
            float4 q4 = *(const float4*)(row + 8);
            float2 rr[10];
            rr[0] = make_float2(q0.x, q0.y); rr[1] = make_float2(q0.z, q0.w);
            rr[2] = make_float2(q1.x, q1.y); rr[3] = make_float2(q1.z, q1.w);
            rr[4] = make_float2(q2.x, q2.y); rr[5] = make_float2(q2.z, q2.w);
            rr[6] = make_float2(q3.x, q3.y); rr[7] = make_float2(q3.z, q3.w);
            rr[8] = make_float2(q4.x, q4.y); rr[9] = make_float2(q4.z, q4.w);
            const float2* wr = wp + (dz * 7 + dy) * 7;
            #pragma unroll
            for (int dx = 0; dx < 7; dx++) {
                float2 w = wr[dx];
                acc0 = ffma2(rr[dx + 0], w, acc0);
                acc1 = ffma2(rr[dx + 1], w, acc1);
                acc2 = ffma2(rr[dx + 2], w, acc2);
                acc3 = ffma2(rr[dx + 3], w, acc3);
            }
        }
    }

    // transpose through smem to token-major, write compacted channels-last
    int widx = z * 16 + yy * 4;
    sOut[(widx + 0) * 16 + 2 * p] = acc0.x; sOut[(widx + 0) * 16 + 2 * p + 1] = acc0.y;
    sOut[(widx + 1) * 16 + 2 * p] = acc1.x; sOut[(widx + 1) * 16 + 2 * p + 1] = acc1.y;
    sOut[(widx + 2) * 16 + 2 * p] = acc2.x; sOut[(widx + 2) * 16 + 2 * p + 1] = acc2.y;
    sOut[(widx + 3) * 16 + 2 * p] = acc3.x; sOut[(widx + 3) * 16 + 2 * p + 1] = acc3.y;
    __syncthreads();

    float* yout = g_yc + (size_t)cellSlot * CELLTOK * CH + c0;
    #pragma unroll
    for (int k = 0; k < 8; k++) {
        int i  = k * 128 + tid;
        int w  = i >> 4;
        int ch = i & 15;
        yout[(size_t)w * CH + ch] = sOut[w * 16 + ch];
    }
}

// ---------------------------------------------------------------------------
// Kernel 2: fused LayerNorm + GEMM1 (tf32 mma) + exact gelu -> g_h
// One cell per block. 256 threads = 8 warps (4M x 2N), N chunks of 64.
// ---------------------------------------------------------------------------
#define SA1 196
#define SB1 68
#define SMEM1 ((64 * SA1 + 192 * SB1) * 4)   // 102400 B

__global__ __launch_bounds__(256)
void mlp1_kernel(const float* __restrict__ ln_w, const float* __restrict__ ln_b,
                 const float* __restrict__ w1,   const float* __restrict__ b1) {
    int cellSlot = blockIdx.x;
    if (cellSlot >= g_cellCount) return;

    extern __shared__ float sm1[];
    float* sA = sm1;                 // [64][196]
    float* sB = sm1 + 64 * SA1;      // [192][68]

    int tid = threadIdx.x;
    const float* yrow = g_yc + (size_t)cellSlot * CELLTOK * CH;

    // load y tile (contiguous float4)
    for (int i = tid; i < 64 * 48; i += 256) {
        int r = i / 48, cq = i - r * 48;
        float4 v = *(const float4*)(yrow + (size_t)r * CH + cq * 4);
        *(float4*)&sA[r * SA1 + cq * 4] = v;
    }
    __syncthreads();

    // LayerNorm (4 threads per token row) + tf32 round in place
    {
        int row = tid >> 2, q = tid & 3;
        float* ar = &sA[row * SA1 + q * 48];
        float s = 0.f, ss = 0.f;
        #pragma unroll
        for (int i = 0; i < 48; i++) { float v = ar[i]; s += v; ss += v * v; }
        s  += __shfl_xor_sync(0xffffffffu, s, 1);
        ss += __shfl_xor_sync(0xffffffffu, ss, 1);
        s  += __shfl_xor_sync(0xffffffffu, s, 2);
        ss += __shfl_xor_sync(0xffffffffu, ss, 2);
        float mu   = s * (1.0f / 192.0f);
        float var  = ss * (1.0f / 192.0f) - mu * mu;
        float rstd = rsqrtf(var + 1e-6f);
        #pragma unroll
        for (int i = 0; i < 48; i++) {
            int c = q * 48 + i;
            float v = (ar[i] - mu) * rstd * __ldg(ln_w + c) + __ldg(ln_b + c);
            ar[i] = tf32r(v);
        }
    }
    __syncthreads();

    int wid = tid >> 5, lane = tid & 31;
    int g = lane >> 2, tg = lane & 3;
    int m0 = (wid >> 1) * 16;
    int nw = (wid & 1) * 32;
    float* hout = g_h + (size_t)cellSlot * CELLTOK * HID;

    for (int nc = 0; nc < 12; nc++) {
        int n0 = nc * 64;
        // stage w1 chunk [192][64], tf32-rounded
        for (int i = tid; i < 192 * 16; i += 256) {
            int k = i >> 4, nq = i & 15;
            float4 v = *(const float4*)(w1 + (size_t)k * HID + n0 + nq * 4);
            v.x = tf32r(v.x); v.y = tf32r(v.y); v.z = tf32r(v.z); v.w = tf32r(v.w);
            *(float4*)&sB[k * SB1 + nq * 4] = v;
        }
        __syncthreads();

        float c1[4][4];
        #pragma unroll
        for (int s = 0; s < 4; s++)
            #pragma unroll
            for (int e = 0; e < 4; e++) c1[s][e] = 0.f;

        for (int ks = 0; ks < 24; ks++) {
            int k0 = ks * 8;
            float av[4];
            av[0] = sA[(m0 + g) * SA1 + k0 + tg];
            av[1] = sA[(m0 + g + 8) * SA1 + k0 + tg];
            av[2] = sA[(m0 + g) * SA1 + k0 + tg + 4];
            av[3] = sA[(m0 + g + 8) * SA1 + k0 + tg + 4];
            #pragma unroll
            for (int sub = 0; sub < 4; sub++) {
                float b0 = sB[(k0 + tg) * SB1 + nw + sub * 8 + g];
                float b1v = sB[(k0 + tg + 4) * SB1 + nw + sub * 8 + g];
                mma_tf32(c1[sub], av, b0, b1v);
            }
        }

        // epilogue: +b1, gelu, tf32 round, write H
        #pragma unroll
        for (int sub = 0; sub < 4; sub++) {
            int n = n0 + nw + sub * 8 + 2 * tg;
            float bb0 = __ldg(b1 + n), bb1 = __ldg(b1 + n + 1);
            int r0 = m0 + g, r1 = m0 + g + 8;
            hout[(size_t)r0 * HID + n]     = tf32r(gelu_exact(c1[sub][0] + bb0));
            hout[(size_t)r0 * HID + n + 1] = tf32r(gelu_exact(c1[sub][1] + bb1));
            hout[(size_t)r1 * HID + n]     = tf32r(gelu_exact(c1[sub][2] + bb0));
            hout[(size_t)r1 * HID + n + 1] = tf32r(gelu_exact(c1[sub][3] + bb1));
        }
        __syncthreads();
    }
}

// ---------------------------------------------------------------------------
// Kernel 3: GEMM2 (tf32 mma) + b2 + gamma, scatter to dense NCDHW output.
// One cell per block. 256 threads = 8 warps (4M x 2N), K chunks of 32.
// ---------------------------------------------------------------------------
#define SA2 36
#define SB2 196
#define SMEM2 (64 * 196 * 4)   // 50176 B (covers staging + transpose buffer)

__global__ __launch_bounds__(256)
void mlp2_kernel(const float* __restrict__ w2, const float* __restrict__ b2,
                 const float* __restrict__ gamma, float* __restrict__ out) {
    int cellSlot = blockIdx.x;
    if (cellSlot >= g_cellCount) return;
    int cell = g_cellList[cellSlot];
    int b  = cell >> 9;
    int cz = (cell >> 6) & 7, cy = (cell >> 3) & 7, cx = cell & 7;
    int z0 = cz * 4, y0 = cy * 4, x0 = cx * 4;

    extern __shared__ float sm2[];
    float* sA = sm2;                 // [64][36]
    float* sB = sm2 + 64 * SA2;      // [32][196]
    float* sO = sm2;                 // [64][196] (reused after compute)

    int tid = threadIdx.x;
    int wid = tid >> 5, lane = tid & 31;
    int g = lane >> 2, tg = lane & 3;
    int m0 = (wid >> 1) * 16;
    int nw = (wid & 1) * 96;

    const float* hrow = g_h + (size_t)cellSlot * CELLTOK * HID;

    float acc[12][4];
    #pragma unroll
    for (int s = 0; s < 12; s++)
        #pragma unroll
        for (int e = 0; e < 4; e++) acc[s][e] = 0.f;

    for (int kc = 0; kc < 24; kc++) {
        int kb = kc * 32;
        // stage H chunk [64][32]
        for (int i = tid; i < 512; i += 256) {
            int r = i >> 3, kq = i & 7;
            float4 v = *(const float4*)(hrow + (size_t)r * HID + kb + kq * 4);
            *(float4*)&sA[r * SA2 + kq * 4] = v;
        }
        // stage w2 chunk [32][192], tf32-rounded
        for (int i = tid; i < 1536; i += 256) {
            int k = i / 48, nq = i - k * 48;
            float4 v = *(const float4*)(w2 + (size_t)(kb + k) * CH + nq * 4);
            v.x = tf32r(v.x); v.y = tf32r(v.y); v.z = tf32r(v.z); v.w = tf32r(v.w);
            *(float4*)&sB[k * SB2 + nq * 4] = v;
        }
        __syncthreads();

        #pragma unroll
        for (int ks = 0; ks < 4; ks++) {
            int k0 = ks * 8;
            float av[4];
            av[0] = sA[(m0 + g) * SA2 + k0 + tg];
            av[1] = sA[(m0 + g + 8) * SA2 + k0 + tg];
            av[2] = sA[(m0 + g) * SA2 + k0 + tg + 4];
            av[3] = sA[(m0 + g + 8) * SA2 + k0 + tg + 4];
            #pragma unroll
            for (int sub = 0; sub < 12; sub++) {
                float b0 = sB[(k0 + tg) * SB2 + nw + sub * 8 + g];
                float b1v = sB[(k0 + tg + 4) * SB2 + nw + sub * 8 + g];
                mma_tf32(acc[sub], av, b0, b1v);
            }
        }
        __syncthreads();
    }

    // epilogue: +b2, *gamma, into smem token-major
    #pragma unroll
    for (int sub = 0; sub < 12; sub++) {
        int n = nw + sub * 8 + 2 * tg;
        float g0 = __ldg(gamma + n), g1 = __ldg(gamma + n + 1);
        float bb0 = __ldg(b2 + n),   bb1 = __ldg(b2 + n + 1);
        sO[(m0 + g) * SB2 + n]         = g0 * (acc[sub][0] + bb0);
        sO[(m0 + g) * SB2 + n + 1]     = g1 * (acc[sub][1] + bb1);
        sO[(m0 + g + 8) * SB2 + n]     = g0 * (acc[sub][2] + bb0);
        sO[(m0 + g + 8) * SB2 + n + 1] = g1 * (acc[sub][3] + bb1);
    }
    __syncthreads();

    // coalesced scatter: per (c, z, y) write float4 along x
    for (int i = tid; i < 3072; i += 256) {
        int c = i >> 4, r = i & 15;
        int z = r >> 2, y = r & 3;
        int tok = z * 16 + y * 4;
        float4 v;
        v.x = sO[(tok + 0) * SB2 + c];
        v.y = sO[(tok + 1) * SB2 + c];
        v.z = sO[(tok + 2) * SB2 + c];
        v.w = sO[(tok + 3) * SB2 + c];
        size_t off = ((size_t)(b * CH + c)) * SPAT + (size_t)(z0 + z) * 1024
                   + (size_t)(y0 + y) * 32 + x0;
        *(float4*)(out + off) = v;
    }
}

// ---------------------------------------------------------------------------
// Launch
// ---------------------------------------------------------------------------
extern "C" void kernel_launch(void* const* d_in, const int* in_sizes, int n_in,
                              void* d_out, int out_size) {
    const float* x     = (const float*)d_in[0];
    const void*  mask  = d_in[1];
    const float* dw_w  = (const float*)d_in[2];
    const float* dw_b  = (const float*)d_in[3];
    const float* ln_w  = (const float*)d_in[4];
    const float* ln_b  = (const float*)d_in[5];
    const float* w1    = (const float*)d_in[6];
    const float* b1    = (const float*)d_in[7];
    const float* w2    = (const float*)d_in[8];
    const float* b2    = (const float*)d_in[9];
    const float* gamma = (const float*)d_in[10];
    float* out = (float*)d_out;

    cudaFuncSetAttribute(conv_kernel, cudaFuncAttributeMaxDynamicSharedMemorySize, CONV_SMEM);
    cudaFuncSetAttribute(mlp1_kernel, cudaFuncAttributeMaxDynamicSharedMemorySize, SMEM1);
    cudaFuncSetAttribute(mlp2_kernel, cudaFuncAttributeMaxDynamicSharedMemorySize, SMEM2);

    cudaMemsetAsync(d_out, 0, (size_t)out_size * sizeof(float));
    build_cells_kernel<<<1, 1024>>>(mask);
    conv_kernel<<<NCELLS * 12, 128, CONV_SMEM>>>(x, dw_w, dw_b);
    mlp1_kernel<<<NCELLS, 256, SMEM1>>>(ln_w, ln_b, w1, b1);
    mlp2_kernel<<<NCELLS, 256, SMEM2>>>(w2, b2, gamma, out);
}